// round 16
// baseline (speedup 1.0000x reference)
#include <cuda_runtime.h>
#include <cuda_fp16.h>
#include <stdint.h>

#define T_STEPS 1024
#define BATCH   128
#define INDIM   6
#define HDIM    1536
#define OUTDIM  5
#define WELEMS  (4*HDIM*HDIM)     // 9437184

#define NCTA     128
#define NC       12               // h-columns per CTA
#define NLOC     48               // gate rows per CTA (4*NC)
#define NTHREADS 576
#define NCOMP    512              // warps 0-15 compute (2 K-halves x 8)
#define NLDR     64               // warps 16-17 load

#define KC       128              // halfs per K stage (256 B rows)
#define RB       256
#define NCHUNK   (HDIM/KC)        // 12 chunks per 1536-K GEMM
#define NSTAGE   4
#define A_BYTES  (128*RB)         // 32768
#define B_BYTES  (NLOC*RB)        // 12288
#define STAGE_BYTES (A_BYTES + B_BYTES)        // 45056
#define OFF_GATES   (NSTAGE*STAGE_BYTES)       // 180224 (half-0 partials)
#define OFF_GR      (OFF_GATES + 128*NLOC*4)   // 204800 (half-1 partials)
#define OFF_WX      (OFF_GR + 128*NLOC*4)      // 229376
#define OFF_B0      (OFF_WX + NLOC*INDIM*4)
#define OFF_B1      (OFF_B0 + NLOC*4)
#define OFF_MBAR    (OFF_B1 + NLOC*4)          // 8-aligned
#define SMEM_DYN    (OFF_MBAR + 128)           // 231040 B (< 232448 limit)

// ---------------- device globals ---------------------------------------------
__device__ __align__(128) __half g_Whh0[WELEMS];
__device__ __align__(128) __half g_Wih1[WELEMS];
__device__ __align__(128) __half g_Whh1[WELEMS];
__device__ __align__(128) __half g_h0[2][BATCH*HDIM];
__device__ __align__(128) __half g_h1[2][BATCH*HDIM];
__device__ __align__(128) float  g_h1f[BATCH*HDIM];
__device__ unsigned g_bar0, g_bar1;

// ---------------- weight convert + barrier reset -----------------------------
__global__ void convert_kernel(const float* __restrict__ whh0,
                               const float* __restrict__ wih1,
                               const float* __restrict__ whh1) {
    long i = (long)blockIdx.x * blockDim.x + threadIdx.x;
    if (i == 0) { g_bar0 = 0u; g_bar1 = 0u; }
    if (i < (long)WELEMS)            g_Whh0[i]             = __float2half_rn(whh0[i]);
    else if (i < 2L*WELEMS)          g_Wih1[i - WELEMS]    = __float2half_rn(wih1[i - WELEMS]);
    else if (i < 3L*WELEMS)          g_Whh1[i - 2L*WELEMS] = __float2half_rn(whh1[i - 2L*WELEMS]);
}

// ---------------- PTX helpers -------------------------------------------------
__device__ __forceinline__ void cpa16(uint32_t s, const void* g) {
    asm volatile("cp.async.cg.shared.global [%0], [%1], 16;\n" :: "r"(s), "l"(g) : "memory");
}
__device__ __forceinline__ void cp_commit() { asm volatile("cp.async.commit_group;\n" ::: "memory"); }
__device__ __forceinline__ void cp_wait1()  { asm volatile("cp.async.wait_group 1;\n" ::: "memory"); }
__device__ __forceinline__ void cp_wait0()  { asm volatile("cp.async.wait_group 0;\n" ::: "memory"); }

__device__ __forceinline__ void mbar_init(uint32_t mbar, uint32_t cnt) {
    asm volatile("mbarrier.init.shared.b64 [%0], %1;" :: "r"(mbar), "r"(cnt) : "memory");
}
__device__ __forceinline__ void mbar_arrive(uint32_t mbar) {
    asm volatile("mbarrier.arrive.shared.b64 _, [%0];" :: "r"(mbar) : "memory");
}
__device__ __forceinline__ void mbar_wait(uint32_t mbar, uint32_t phase) {
    asm volatile(
        "{\n\t.reg .pred P;\n\t"
        "WL%=:\n\t"
        "mbarrier.try_wait.parity.shared::cta.b64 P, [%0], %1, 0x989680;\n\t"
        "@P bra WD%=;\n\t"
        "bra WL%=;\n\t"
        "WD%=:\n\t}"
        :: "r"(mbar), "r"(phase) : "memory");
}
__device__ __forceinline__ void ldsm_x4(uint32_t* r, uint32_t addr) {
    asm volatile("ldmatrix.sync.aligned.m8n8.x4.shared.b16 {%0,%1,%2,%3}, [%4];\n"
                 : "=r"(r[0]), "=r"(r[1]), "=r"(r[2]), "=r"(r[3]) : "r"(addr));
}
__device__ __forceinline__ void ldsm_x2(uint32_t* r, uint32_t addr) {
    asm volatile("ldmatrix.sync.aligned.m8n8.x2.shared.b16 {%0,%1}, [%2];\n"
                 : "=r"(r[0]), "=r"(r[1]) : "r"(addr));
}
__device__ __forceinline__ void mma16816(float* d, const uint32_t* a, uint32_t b0, uint32_t b1) {
    asm volatile(
        "mma.sync.aligned.m16n8k16.row.col.f32.f16.f16.f32 "
        "{%0,%1,%2,%3}, {%4,%5,%6,%7}, {%8,%9}, {%0,%1,%2,%3};\n"
        : "+f"(d[0]), "+f"(d[1]), "+f"(d[2]), "+f"(d[3])
        : "r"(a[0]), "r"(a[1]), "r"(a[2]), "r"(a[3]), "r"(b0), "r"(b1));
}
#define NBAR() asm volatile("bar.sync 1, %0;" :: "n"(NCOMP) : "memory")

__device__ __forceinline__ float sigm(float x)  { return __fdividef(1.0f, 1.0f + __expf(-x)); }
__device__ __forceinline__ float tanh_f(float x){ return __fdividef(2.0f, 1.0f + __expf(-2.0f*x)) - 1.0f; }

// loader-side chip-barrier poll (per warp: lane 0 polls)
__device__ __forceinline__ void lwait(unsigned* bar, unsigned target, int lane) {
    if (lane == 0) {
        unsigned v;
        do {
            asm volatile("ld.volatile.global.u32 %0, [%1];" : "=r"(v) : "l"(bar));
            if (v >= target) break;
            __nanosleep(64);
        } while (true);
    }
    __syncwarp();
}

// ---------------- compute-side context ----------------------------------------
// 16 compute warps: 4m x 2n grid x 2 K-halves. Warp tile m32 x n24; each warp
// consumes 4 of the 8 k16-slices of EVERY chunk (slice-split, not chunk-split).
struct Ctx {
    uint32_t aA0, aA1, aB4, aB2;
    uint32_t cq4[4], cq2[4];    // 4 slices owned by this warp
    int gid, tig, wm, wn, half;
};

__device__ __forceinline__ void compute_stage(uint32_t sb, int buf, const Ctx& c,
                                              float acc[2][3][4]) {
    uint32_t stage  = sb + (uint32_t)buf * STAGE_BYTES;
    uint32_t bstage = stage + A_BYTES;
#pragma unroll
    for (int q = 0; q < 4; q++) {
        uint32_t ra[2][4], rb[4], rb2[2];
        ldsm_x4(ra[0], stage + c.aA0 + c.cq4[q]);
        ldsm_x4(ra[1], stage + c.aA1 + c.cq4[q]);
        ldsm_x4(rb,    bstage + c.aB4 + c.cq4[q]);
        ldsm_x2(rb2,   bstage + c.aB2 + c.cq2[q]);
#pragma unroll
        for (int tm = 0; tm < 2; tm++) {
            mma16816(acc[tm][0], ra[tm], rb[0],  rb[2]);
            mma16816(acc[tm][1], ra[tm], rb[1],  rb[3]);
            mma16816(acc[tm][2], ra[tm], rb2[0], rb2[1]);
        }
    }
}

__device__ __forceinline__ void store_gates(float* dst, const Ctx& c,
                                            const float acc[2][3][4]) {
#pragma unroll
    for (int tm = 0; tm < 2; tm++)
#pragma unroll
        for (int tn = 0; tn < 3; tn++) {
            int row = c.wm*32 + tm*16 + c.gid;
            int n   = c.wn*24 + tn*8 + c.tig*2;
            float* p0 = dst + row*NLOC + n;
            p0[0] = acc[tm][tn][0]; p0[1] = acc[tm][tn][1];
            float* p1 = dst + (row + 8)*NLOC + n;
            p1[0] = acc[tm][tn][2]; p1[1] = acc[tm][tn][3];
        }
}

// consume `n` chunks from the ring (every chunk, half the slices)
__device__ __forceinline__ void consume(uint32_t sb, const Ctx& c, int lane,
                                        int n, int& cc, float acc[2][3][4]) {
#pragma unroll 1
    for (int s = 0; s < n; s++, cc++) {
        int st = cc & 3;
        mbar_wait(sb + OFF_MBAR + st*8, (uint32_t)((cc >> 2) & 1));
        compute_stage(sb, st, c, acc);
        __syncwarp();
        if (lane == 0) mbar_arrive(sb + OFF_MBAR + 32 + st*8);
    }
}

// ---------------- loader state ------------------------------------------------
struct Ldr {
    int r0, gA_base;
    uint32_t colE, colO;
    int wB[12];
    int lcc;
    int prev;
};

__device__ __forceinline__ void produce(uint32_t sb, Ldr& L,
                                        const __half* __restrict__ A,
                                        const __half* __restrict__ W, int k0) {
    int st = L.lcc & 3;
    mbar_wait(sb + OFF_MBAR + 32 + st*8, (uint32_t)(((L.lcc >> 2) & 1) ^ 1));
    uint32_t sbuf = sb + (uint32_t)st * STAGE_BYTES;
    const __half* gA = A + L.gA_base + k0;
#pragma unroll
    for (int i = 0; i < 32; i++) {
        uint32_t off = (uint32_t)((L.r0 + 4*i) * RB) + ((i & 1) ? L.colO : L.colE);
        cpa16(sbuf + off, gA + (size_t)i*4*HDIM);
    }
    uint32_t bb = sbuf + A_BYTES;
#pragma unroll
    for (int i = 0; i < 12; i++) {
        uint32_t off = (uint32_t)((L.r0 + 4*i) * RB) + ((i & 1) ? L.colO : L.colE);
        cpa16(bb + off, W + L.wB[i] + k0);
    }
    cp_commit();
    if (L.prev >= 0) {
        cp_wait1();
        mbar_arrive(sb + OFF_MBAR + L.prev*8);
    }
    L.prev = st;
    L.lcc++;
}

__device__ __forceinline__ void lflush(uint32_t sb, Ldr& L) {
    if (L.prev >= 0) {
        cp_wait0();
        mbar_arrive(sb + OFF_MBAR + L.prev*8);
        L.prev = -1;
    }
}

// ---------------- persistent LSTM kernel -------------------------------------
__global__ void __launch_bounds__(NTHREADS, 1)
lstm_kernel(const float* __restrict__ x,
            const float* __restrict__ Wih0,
            const float* __restrict__ bih0, const float* __restrict__ bhh0,
            const float* __restrict__ bih1, const float* __restrict__ bhh1,
            const float* __restrict__ Wlin, const float* __restrict__ blin,
            float* __restrict__ out) {
    extern __shared__ unsigned char dsm[];
    const int tid  = threadIdx.x;
    const int lane = tid & 31;
    const int j0   = blockIdx.x * NC;
    const uint32_t sb = (uint32_t)__cvta_generic_to_shared(dsm);
    float* sG  = (float*)(dsm + OFF_GATES);
    float* sGr = (float*)(dsm + OFF_GR);
    float* sWx = (float*)(dsm + OFF_WX);
    float* sB0 = (float*)(dsm + OFF_B0);
    float* sB1 = (float*)(dsm + OFF_B1);

    // ---- mbarrier init ----
    if (tid == 0) {
#pragma unroll
        for (int s = 0; s < NSTAGE; s++) {
            mbar_init(sb + OFF_MBAR + s*8, NLDR);       // full: 64 loader arrivals
            mbar_init(sb + OFF_MBAR + 32 + s*8, 16);    // free: 16 warp arrivals
        }
    }

    // ---- constants ----
    for (int n = tid; n < NLOC; n += NTHREADS) {
        int grow = (n / NC) * HDIM + j0 + (n % NC);
        sB0[n] = bih0[grow] + bhh0[grow];
        sB1[n] = bih1[grow] + bhh1[grow];
#pragma unroll
        for (int k = 0; k < INDIM; k++) sWx[n*INDIM + k] = Wih0[grow*INDIM + k];
    }

    // ---- zero initial h state ----
    for (int e = tid; e < BATCH*NC; e += NTHREADS) {
        int b = e / NC, j = e % NC;
        int idx = b*HDIM + j0 + j;
        g_h0[0][idx] = __float2half_rn(0.0f);
        g_h1[0][idx] = __float2half_rn(0.0f);
    }
    __threadfence();
    __syncthreads();
    if (tid == 0) {
        asm volatile("red.global.gpu.add.u32 [%0], 1;" :: "l"(&g_bar0) : "memory");
        asm volatile("red.global.gpu.add.u32 [%0], 1;" :: "l"(&g_bar1) : "memory");
    }

    if (tid < NCOMP) {
        // =================== COMPUTE ROLE (warps 0-15) ===================
        Ctx c;
        {
            int warp = tid >> 5;
            c.gid = lane >> 2; c.tig = lane & 3;
            c.wm = warp & 3;  c.wn = (warp >> 2) & 1;  c.half = warp >> 3;
            int r16 = lane & 15, hi = lane >> 4, xv = lane & 7;
            c.aA0 = (uint32_t)((c.wm*32 + r16) * RB);
            c.aA1 = c.aA0 + 16*RB;
            c.aB4 = (uint32_t)((c.wn*24 + r16) * RB);
            c.aB2 = (uint32_t)((c.wn*24 + 16 + xv) * RB);
            int hi2 = (lane >> 3) & 1;
#pragma unroll
            for (int q = 0; q < 4; q++) {
                int u4 = 2*(c.half*4 + q) + hi;
                int u2 = 2*(c.half*4 + q) + hi2;
                c.cq4[q] = (uint32_t)((((u4 & 7) ^ xv) << 4) + ((u4 >> 3) << 7));
                c.cq2[q] = (uint32_t)((((u2 & 7) ^ xv) << 4) + ((u2 >> 3) << 7));
            }
        }
        float* sMine = c.half ? sGr : sG;
        float cr0[3], cr1[3];
#pragma unroll
        for (int i = 0; i < 3; i++) { cr0[i] = 0.0f; cr1[i] = 0.0f; }
        int cc = 0;

#pragma unroll 1
        for (int t = 0; t < T_STEPS; t++) {
            const int p = t & 1;
            float acc[2][3][4];

            // -------- G_A: Whh0 * h0[p] --------
#pragma unroll
            for (int a = 0; a < 2; a++)
#pragma unroll
                for (int b = 0; b < 3; b++)
#pragma unroll
                    for (int d = 0; d < 4; d++) acc[a][b][d] = 0.0f;
            consume(sb, c, lane, NCHUNK, cc, acc);
            store_gates(sMine, c, acc);
            NBAR();

            // -------- epilogue 0 (sum the two K-half partials) --------
            {
                const float* xt = x + (size_t)t * BATCH * INDIM;
#pragma unroll
                for (int i = 0; i < 3; i++) {
                    int e = tid + i*NCOMP;
                    int b = e / NC, j = e % NC;
                    float iv = sG[b*NLOC + j]        + sGr[b*NLOC + j]        + sB0[j];
                    float fv = sG[b*NLOC + NC + j]   + sGr[b*NLOC + NC + j]   + sB0[NC + j];
                    float gv = sG[b*NLOC + 2*NC + j] + sGr[b*NLOC + 2*NC + j] + sB0[2*NC + j];
                    float ov = sG[b*NLOC + 3*NC + j] + sGr[b*NLOC + 3*NC + j] + sB0[3*NC + j];
                    const float* xr = xt + b*INDIM;
#pragma unroll
                    for (int k = 0; k < INDIM; k++) {
                        float xk = xr[k];
                        iv += xk * sWx[j*INDIM + k];
                        fv += xk * sWx[(NC + j)*INDIM + k];
                        gv += xk * sWx[(2*NC + j)*INDIM + k];
                        ov += xk * sWx[(3*NC + j)*INDIM + k];
                    }
                    float cn = sigm(fv)*cr0[i] + sigm(iv)*tanh_f(gv);
                    cr0[i] = cn;
                    g_h0[p ^ 1][(size_t)b*HDIM + j0 + j] = __float2half_rn(sigm(ov)*tanh_f(cn));
                }
            }
            __threadfence();
            NBAR();
            if (tid == 0)
                asm volatile("red.global.gpu.add.u32 [%0], 1;" :: "l"(&g_bar0) : "memory");

            // -------- fused G_C+G_D: Whh1*h1[p] + Wih1*h0[t] --------
#pragma unroll
            for (int a = 0; a < 2; a++)
#pragma unroll
                for (int b = 0; b < 3; b++)
#pragma unroll
                    for (int d = 0; d < 4; d++) acc[a][b][d] = 0.0f;
            consume(sb, c, lane, 2*NCHUNK, cc, acc);
            store_gates(sMine, c, acc);
            NBAR();

            // -------- epilogue 1 --------
            {
                const bool last = (t == T_STEPS - 1);
#pragma unroll
                for (int i = 0; i < 3; i++) {
                    int e = tid + i*NCOMP;
                    int b = e / NC, j = e % NC;
                    float iv = sG[b*NLOC + j]        + sGr[b*NLOC + j]        + sB1[j];
                    float fv = sG[b*NLOC + NC + j]   + sGr[b*NLOC + NC + j]   + sB1[NC + j];
                    float gv = sG[b*NLOC + 2*NC + j] + sGr[b*NLOC + 2*NC + j] + sB1[2*NC + j];
                    float ov = sG[b*NLOC + 3*NC + j] + sGr[b*NLOC + 3*NC + j] + sB1[3*NC + j];
                    float cn = sigm(fv)*cr1[i] + sigm(iv)*tanh_f(gv);
                    cr1[i] = cn;
                    float hn = sigm(ov)*tanh_f(cn);
                    g_h1[p ^ 1][(size_t)b*HDIM + j0 + j] = __float2half_rn(hn);
                    if (last) g_h1f[(size_t)b*HDIM + j0 + j] = hn;
                }
            }
            __threadfence();
            NBAR();
            if (tid == 0)
                asm volatile("red.global.gpu.add.u32 [%0], 1;" :: "l"(&g_bar1) : "memory");
        }

        // -------- final linear (CTA 0) --------
        if (blockIdx.x == 0) {
            if (tid == 0) {
                unsigned v;
                do {
                    asm volatile("ld.volatile.global.u32 %0, [%1];" : "=r"(v) : "l"(&g_bar1));
                    if (v >= (unsigned)(NCTA*(T_STEPS + 1))) break;
                    __nanosleep(64);
                } while (true);
            }
            NBAR();
#pragma unroll 1
            for (int e = tid; e < BATCH*OUTDIM; e += NCOMP) {
                int b = e / OUTDIM, o = e % OUTDIM;
                float s = blin[o];
                const float* hr = g_h1f + (size_t)b*HDIM;
                const float* wr = Wlin + (size_t)o*HDIM;
#pragma unroll 4
                for (int k = 0; k < HDIM; k++) s += hr[k] * wr[k];
                out[b*OUTDIM + o] = s;
            }
        }
    } else {
        // =================== LOADER ROLE (warps 16-17) ===================
        Ldr L;
        {
            const int lid = tid - NCOMP;            // 0..63
            L.r0  = lid >> 4;                       // 0..3
            const int s16 = lid & 15;
            const int s7  = s16 & 7;
            const uint32_t sHi = (uint32_t)((s16 >> 3) << 7);
            L.colE = sHi + (uint32_t)((s7 ^ L.r0) << 4);
            L.colO = sHi + (uint32_t)((s7 ^ (L.r0 + 4)) << 4);
            L.gA_base = L.r0*HDIM + s16*8;
#pragma unroll
            for (int i = 0; i < 12; i++) {
                int r = L.r0 + 4*i;
                L.wB[i] = ((r / NC) * HDIM + j0 + (r % NC)) * HDIM + s16*8;
            }
            L.lcc = 0;
            L.prev = -1;
        }

#pragma unroll 1
        for (int t = 0; t < T_STEPS; t++) {
            const int p = t & 1;
            lwait(&g_bar0, (unsigned)(NCTA*(t + 1)), lane);
#pragma unroll 1
            for (int s = 0; s < NCHUNK; s++)
                produce(sb, L, g_h0[p], g_Whh0, s*KC);
            lflush(sb, L);
            lwait(&g_bar1, (unsigned)(NCTA*(t + 1)), lane);
#pragma unroll 1
            for (int s = 0; s < NCHUNK; s++)
                produce(sb, L, g_h1[p], g_Whh1, s*KC);
            lflush(sb, L);
            lwait(&g_bar0, (unsigned)(NCTA*(t + 2)), lane);
#pragma unroll 1
            for (int s = 0; s < NCHUNK; s++)
                produce(sb, L, g_h0[p ^ 1], g_Wih1, s*KC);
            lflush(sb, L);
        }
    }
}

// ---------------- launch ------------------------------------------------------
extern "C" void kernel_launch(void* const* d_in, const int* in_sizes, int n_in,
                              void* d_out, int out_size) {
    const float* x    = (const float*)d_in[0];
    const float* Wih0 = (const float*)d_in[1];
    const float* Whh0 = (const float*)d_in[2];
    const float* bih0 = (const float*)d_in[3];
    const float* bhh0 = (const float*)d_in[4];
    const float* Wih1 = (const float*)d_in[5];
    const float* Whh1 = (const float*)d_in[6];
    const float* bih1 = (const float*)d_in[7];
    const float* bhh1 = (const float*)d_in[8];
    const float* Wlin = (const float*)d_in[9];
    const float* blin = (const float*)d_in[10];

    cudaFuncSetAttribute(lstm_kernel, cudaFuncAttributeMaxDynamicSharedMemorySize, SMEM_DYN);

    int cblocks = (3*WELEMS + 255) / 256;
    convert_kernel<<<cblocks, 256>>>(Whh0, Wih1, Whh1);
    lstm_kernel<<<NCTA, NTHREADS, SMEM_DYN>>>(x, Wih0, bih0, bhh0, bih1, bhh1,
                                              Wlin, blin, (float*)d_out);
}

// round 17
// speedup vs baseline: 1.0711x; 1.0711x over previous
#include <cuda_runtime.h>
#include <cuda_fp16.h>
#include <stdint.h>

#define T_STEPS 1024
#define BATCH   128
#define INDIM   6
#define HDIM    1536
#define OUTDIM  5
#define WELEMS  (4*HDIM*HDIM)     // 9437184

#define NCTA     128
#define NC       12               // h-columns per CTA
#define NLOC     48               // gate rows per CTA (4*NC)
#define NTHREADS 384
#define NCOMP    256              // warps 0-7 compute
#define NLDR     128              // warps 8-11 load (one per SMSP)

#define KC       128              // halfs per K stage (256 B rows)
#define RB       256
#define NCHUNK   (HDIM/KC)        // 12 chunks per 1536-K GEMM
#define NSTAGE   4
#define A_BYTES  (128*RB)         // 32768
#define B_BYTES  (NLOC*RB)        // 12288
#define STAGE_BYTES (A_BYTES + B_BYTES)        // 45056
#define OFF_GATES   (NSTAGE*STAGE_BYTES)       // 180224
#define OFF_WX      (OFF_GATES + 128*NLOC*4)   // 204800
#define OFF_B0      (OFF_WX + NLOC*INDIM*4)
#define OFF_B1      (OFF_B0 + NLOC*4)
#define OFF_MBAR    (OFF_B1 + NLOC*4)          // 8-aligned
#define SMEM_DYN    (OFF_MBAR + 128)           // ~201.7 KB

// ---------------- device globals ---------------------------------------------
__device__ __align__(128) __half g_Whh0[WELEMS];
__device__ __align__(128) __half g_Wih1[WELEMS];
__device__ __align__(128) __half g_Whh1[WELEMS];
__device__ __align__(128) __half g_h0[2][BATCH*HDIM];
__device__ __align__(128) __half g_h1[2][BATCH*HDIM];
__device__ __align__(128) float  g_h1f[BATCH*HDIM];
__device__ unsigned g_bar0, g_bar1;

// ---------------- weight convert + barrier reset -----------------------------
__global__ void convert_kernel(const float* __restrict__ whh0,
                               const float* __restrict__ wih1,
                               const float* __restrict__ whh1) {
    long i = (long)blockIdx.x * blockDim.x + threadIdx.x;
    if (i == 0) { g_bar0 = 0u; g_bar1 = 0u; }
    if (i < (long)WELEMS)            g_Whh0[i]             = __float2half_rn(whh0[i]);
    else if (i < 2L*WELEMS)          g_Wih1[i - WELEMS]    = __float2half_rn(wih1[i - WELEMS]);
    else if (i < 3L*WELEMS)          g_Whh1[i - 2L*WELEMS] = __float2half_rn(whh1[i - 2L*WELEMS]);
}

// ---------------- PTX helpers -------------------------------------------------
__device__ __forceinline__ void cpa16(uint32_t s, const void* g) {
    asm volatile("cp.async.cg.shared.global [%0], [%1], 16;\n" :: "r"(s), "l"(g) : "memory");
}
__device__ __forceinline__ void cp_commit() { asm volatile("cp.async.commit_group;\n" ::: "memory"); }
__device__ __forceinline__ void cp_wait1()  { asm volatile("cp.async.wait_group 1;\n" ::: "memory"); }
__device__ __forceinline__ void cp_wait0()  { asm volatile("cp.async.wait_group 0;\n" ::: "memory"); }

__device__ __forceinline__ void mbar_init(uint32_t mbar, uint32_t cnt) {
    asm volatile("mbarrier.init.shared.b64 [%0], %1;" :: "r"(mbar), "r"(cnt) : "memory");
}
__device__ __forceinline__ void mbar_arrive(uint32_t mbar) {
    asm volatile("mbarrier.arrive.shared.b64 _, [%0];" :: "r"(mbar) : "memory");
}
__device__ __forceinline__ void mbar_wait(uint32_t mbar, uint32_t phase) {
    asm volatile(
        "{\n\t.reg .pred P;\n\t"
        "WL%=:\n\t"
        "mbarrier.try_wait.parity.shared::cta.b64 P, [%0], %1, 0x989680;\n\t"
        "@P bra WD%=;\n\t"
        "bra WL%=;\n\t"
        "WD%=:\n\t}"
        :: "r"(mbar), "r"(phase) : "memory");
}
__device__ __forceinline__ void ldsm_x4(uint32_t* r, uint32_t addr) {
    asm volatile("ldmatrix.sync.aligned.m8n8.x4.shared.b16 {%0,%1,%2,%3}, [%4];\n"
                 : "=r"(r[0]), "=r"(r[1]), "=r"(r[2]), "=r"(r[3]) : "r"(addr));
}
__device__ __forceinline__ void ldsm_x2(uint32_t* r, uint32_t addr) {
    asm volatile("ldmatrix.sync.aligned.m8n8.x2.shared.b16 {%0,%1}, [%2];\n"
                 : "=r"(r[0]), "=r"(r[1]) : "r"(addr));
}
__device__ __forceinline__ void mma16816(float* d, const uint32_t* a, uint32_t b0, uint32_t b1) {
    asm volatile(
        "mma.sync.aligned.m16n8k16.row.col.f32.f16.f16.f32 "
        "{%0,%1,%2,%3}, {%4,%5,%6,%7}, {%8,%9}, {%0,%1,%2,%3};\n"
        : "+f"(d[0]), "+f"(d[1]), "+f"(d[2]), "+f"(d[3])
        : "r"(a[0]), "r"(a[1]), "r"(a[2]), "r"(a[3]), "r"(b0), "r"(b1));
}
#define NBAR() asm volatile("bar.sync 1, %0;" :: "n"(NCOMP) : "memory")

__device__ __forceinline__ float sigm(float x)  { return __fdividef(1.0f, 1.0f + __expf(-x)); }
__device__ __forceinline__ float tanh_f(float x){ return __fdividef(2.0f, 1.0f + __expf(-2.0f*x)) - 1.0f; }

// loader-side chip-barrier poll (per warp: lane 0 polls)
__device__ __forceinline__ void lwait(unsigned* bar, unsigned target, int lane) {
    if (lane == 0) {
        unsigned v;
        do {
            asm volatile("ld.volatile.global.u32 %0, [%1];" : "=r"(v) : "l"(bar));
            if (v >= target) break;
            __nanosleep(64);
        } while (true);
    }
    __syncwarp();
}

// ---------------- compute-side context (R12 layout: 4m x 2n warps) ------------
struct Ctx {
    uint32_t aA0, aA1, aB4, aB2;
    uint32_t cq4[8], cq2[8];
    int gid, tig, wm, wn;
};

__device__ __forceinline__ void compute_stage(uint32_t sb, int buf, const Ctx& c,
                                              float acc[2][3][4]) {
    uint32_t stage  = sb + (uint32_t)buf * STAGE_BYTES;
    uint32_t bstage = stage + A_BYTES;
#pragma unroll
    for (int q = 0; q < 8; q++) {
        uint32_t ra[2][4], rb[4], rb2[2];
        ldsm_x4(ra[0], stage + c.aA0 + c.cq4[q]);
        ldsm_x4(ra[1], stage + c.aA1 + c.cq4[q]);
        ldsm_x4(rb,    bstage + c.aB4 + c.cq4[q]);
        ldsm_x2(rb2,   bstage + c.aB2 + c.cq2[q]);
#pragma unroll
        for (int tm = 0; tm < 2; tm++) {
            mma16816(acc[tm][0], ra[tm], rb[0],  rb[2]);
            mma16816(acc[tm][1], ra[tm], rb[1],  rb[3]);
            mma16816(acc[tm][2], ra[tm], rb2[0], rb2[1]);
        }
    }
}

__device__ __forceinline__ void store_gates(float* sG, const Ctx& c,
                                            const float acc[2][3][4]) {
#pragma unroll
    for (int tm = 0; tm < 2; tm++)
#pragma unroll
        for (int tn = 0; tn < 3; tn++) {
            int row = c.wm*32 + tm*16 + c.gid;
            int n   = c.wn*24 + tn*8 + c.tig*2;
            float* p0 = sG + row*NLOC + n;
            p0[0] = acc[tm][tn][0]; p0[1] = acc[tm][tn][1];
            float* p1 = sG + (row + 8)*NLOC + n;
            p1[0] = acc[tm][tn][2]; p1[1] = acc[tm][tn][3];
        }
}

// consume `n` chunks from the ring (single-chunk granularity)
__device__ __forceinline__ void consume(uint32_t sb, const Ctx& c, int lane,
                                        int n, int& cc, float acc[2][3][4]) {
#pragma unroll 1
    for (int s = 0; s < n; s++, cc++) {
        int st = cc & 3;
        mbar_wait(sb + OFF_MBAR + st*8, (uint32_t)((cc >> 2) & 1));
        compute_stage(sb, st, c, acc);
        __syncwarp();
        if (lane == 0) mbar_arrive(sb + OFF_MBAR + 32 + st*8);
    }
}

// ---------------- loader state ------------------------------------------------
// 128 loader threads (warps 8-11, one per SMSP). Thread owns rows r0+8i
// (r0 = lid>>4 < 8), so the SW128 xor term is constant per thread.
struct Ldr {
    int r0, gA_base;
    uint32_t colA;
    int wB[6];
    int lcc;        // chunk counter
    int prev;       // slot with committed-but-not-arrived loads (-1 none)
};

// issue one chunk (16 A + 6 B cp.asyncs per thread); deferred full-arrive
__device__ __forceinline__ void produce(uint32_t sb, Ldr& L,
                                        const __half* __restrict__ A,
                                        const __half* __restrict__ W, int k0) {
    int st = L.lcc & 3;
    mbar_wait(sb + OFF_MBAR + 32 + st*8, (uint32_t)(((L.lcc >> 2) & 1) ^ 1));
    uint32_t sbuf = sb + (uint32_t)st * STAGE_BYTES;
    const __half* gA = A + L.gA_base + k0;
#pragma unroll
    for (int i = 0; i < 16; i++) {
        cpa16(sbuf + (uint32_t)((L.r0 + 8*i) * RB) + L.colA,
              gA + (size_t)i*8*HDIM);
    }
    uint32_t bb = sbuf + A_BYTES;
#pragma unroll
    for (int i = 0; i < 6; i++) {
        cpa16(bb + (uint32_t)((L.r0 + 8*i) * RB) + L.colA, W + L.wB[i] + k0);
    }
    cp_commit();
    if (L.prev >= 0) {                 // publish previous chunk
        cp_wait1();
        mbar_arrive(sb + OFF_MBAR + L.prev*8);
    }
    L.prev = st;
    L.lcc++;
}

__device__ __forceinline__ void lflush(uint32_t sb, Ldr& L) {
    if (L.prev >= 0) {
        cp_wait0();
        mbar_arrive(sb + OFF_MBAR + L.prev*8);
        L.prev = -1;
    }
}

// ---------------- persistent LSTM kernel -------------------------------------
__global__ void __launch_bounds__(NTHREADS, 1)
lstm_kernel(const float* __restrict__ x,
            const float* __restrict__ Wih0,
            const float* __restrict__ bih0, const float* __restrict__ bhh0,
            const float* __restrict__ bih1, const float* __restrict__ bhh1,
            const float* __restrict__ Wlin, const float* __restrict__ blin,
            float* __restrict__ out) {
    extern __shared__ unsigned char dsm[];
    const int tid  = threadIdx.x;
    const int lane = tid & 31;
    const int j0   = blockIdx.x * NC;
    const uint32_t sb = (uint32_t)__cvta_generic_to_shared(dsm);
    float* sG  = (float*)(dsm + OFF_GATES);
    float* sWx = (float*)(dsm + OFF_WX);
    float* sB0 = (float*)(dsm + OFF_B0);
    float* sB1 = (float*)(dsm + OFF_B1);

    // ---- mbarrier init ----
    if (tid == 0) {
#pragma unroll
        for (int s = 0; s < NSTAGE; s++) {
            mbar_init(sb + OFF_MBAR + s*8, NLDR);       // full: 128 loader arrivals
            mbar_init(sb + OFF_MBAR + 32 + s*8, 8);     // free: 8 warp arrivals
        }
    }

    // ---- constants ----
    for (int n = tid; n < NLOC; n += NTHREADS) {
        int grow = (n / NC) * HDIM + j0 + (n % NC);
        sB0[n] = bih0[grow] + bhh0[grow];
        sB1[n] = bih1[grow] + bhh1[grow];
#pragma unroll
        for (int k = 0; k < INDIM; k++) sWx[n*INDIM + k] = Wih0[grow*INDIM + k];
    }

    // ---- zero initial h state ----
    for (int e = tid; e < BATCH*NC; e += NTHREADS) {
        int b = e / NC, j = e % NC;
        int idx = b*HDIM + j0 + j;
        g_h0[0][idx] = __float2half_rn(0.0f);
        g_h1[0][idx] = __float2half_rn(0.0f);
    }
    __threadfence();
    __syncthreads();
    if (tid == 0) {
        asm volatile("red.global.gpu.add.u32 [%0], 1;" :: "l"(&g_bar0) : "memory");
        asm volatile("red.global.gpu.add.u32 [%0], 1;" :: "l"(&g_bar1) : "memory");
    }

    if (tid < NCOMP) {
        // =================== COMPUTE ROLE (warps 0-7) ===================
        Ctx c;
        {
            int warp = tid >> 5;
            c.gid = lane >> 2; c.tig = lane & 3;
            c.wm = warp & 3;   c.wn = warp >> 2;
            int r16 = lane & 15, hi = lane >> 4, xv = lane & 7;
            c.aA0 = (uint32_t)((c.wm*32 + r16) * RB);
            c.aA1 = c.aA0 + 16*RB;
            c.aB4 = (uint32_t)((c.wn*24 + r16) * RB);
            c.aB2 = (uint32_t)((c.wn*24 + 16 + xv) * RB);
            int hi2 = (lane >> 3) & 1;
#pragma unroll
            for (int q = 0; q < 8; q++) {
                int u4 = 2*q + hi, u2 = 2*q + hi2;
                c.cq4[q] = (uint32_t)((((u4 & 7) ^ xv) << 4) + ((u4 >> 3) << 7));
                c.cq2[q] = (uint32_t)((((u2 & 7) ^ xv) << 4) + ((u2 >> 3) << 7));
            }
        }
        float cr0[6], cr1[6];
#pragma unroll
        for (int i = 0; i < 6; i++) { cr0[i] = 0.0f; cr1[i] = 0.0f; }
        int cc = 0;

#pragma unroll 1
        for (int t = 0; t < T_STEPS; t++) {
            const int p = t & 1;
            float acc[2][3][4];

            // -------- G_A: Whh0 * h0[p] --------
#pragma unroll
            for (int a = 0; a < 2; a++)
#pragma unroll
                for (int b = 0; b < 3; b++)
#pragma unroll
                    for (int d = 0; d < 4; d++) acc[a][b][d] = 0.0f;
            consume(sb, c, lane, NCHUNK, cc, acc);
            store_gates(sG, c, acc);
            NBAR();

            // -------- epilogue 0 --------
            {
                const float* xt = x + (size_t)t * BATCH * INDIM;
#pragma unroll
                for (int i = 0; i < 6; i++) {
                    int e = tid + i*NCOMP;
                    int b = e / NC, j = e % NC;
                    float iv = sG[b*NLOC + j]          + sB0[j];
                    float fv = sG[b*NLOC + NC + j]     + sB0[NC + j];
                    float gv = sG[b*NLOC + 2*NC + j]   + sB0[2*NC + j];
                    float ov = sG[b*NLOC + 3*NC + j]   + sB0[3*NC + j];
                    const float* xr = xt + b*INDIM;
#pragma unroll
                    for (int k = 0; k < INDIM; k++) {
                        float xk = xr[k];
                        iv += xk * sWx[j*INDIM + k];
                        fv += xk * sWx[(NC + j)*INDIM + k];
                        gv += xk * sWx[(2*NC + j)*INDIM + k];
                        ov += xk * sWx[(3*NC + j)*INDIM + k];
                    }
                    float cn = sigm(fv)*cr0[i] + sigm(iv)*tanh_f(gv);
                    cr0[i] = cn;
                    g_h0[p ^ 1][(size_t)b*HDIM + j0 + j] = __float2half_rn(sigm(ov)*tanh_f(cn));
                }
            }
            __threadfence();
            NBAR();
            if (tid == 0)
                asm volatile("red.global.gpu.add.u32 [%0], 1;" :: "l"(&g_bar0) : "memory");

            // -------- fused G_C+G_D: Whh1*h1[p] + Wih1*h0[t] --------
#pragma unroll
            for (int a = 0; a < 2; a++)
#pragma unroll
                for (int b = 0; b < 3; b++)
#pragma unroll
                    for (int d = 0; d < 4; d++) acc[a][b][d] = 0.0f;
            consume(sb, c, lane, 2*NCHUNK, cc, acc);
            store_gates(sG, c, acc);
            NBAR();

            // -------- epilogue 1 --------
            {
                const bool last = (t == T_STEPS - 1);
#pragma unroll
                for (int i = 0; i < 6; i++) {
                    int e = tid + i*NCOMP;
                    int b = e / NC, j = e % NC;
                    float iv = sG[b*NLOC + j]          + sB1[j];
                    float fv = sG[b*NLOC + NC + j]     + sB1[NC + j];
                    float gv = sG[b*NLOC + 2*NC + j]   + sB1[2*NC + j];
                    float ov = sG[b*NLOC + 3*NC + j]   + sB1[3*NC + j];
                    float cn = sigm(fv)*cr1[i] + sigm(iv)*tanh_f(gv);
                    cr1[i] = cn;
                    float hn = sigm(ov)*tanh_f(cn);
                    g_h1[p ^ 1][(size_t)b*HDIM + j0 + j] = __float2half_rn(hn);
                    if (last) g_h1f[(size_t)b*HDIM + j0 + j] = hn;
                }
            }
            __threadfence();
            NBAR();
            if (tid == 0)
                asm volatile("red.global.gpu.add.u32 [%0], 1;" :: "l"(&g_bar1) : "memory");
        }

        // -------- final linear (CTA 0) --------
        if (blockIdx.x == 0) {
            if (tid == 0) {
                unsigned v;
                do {
                    asm volatile("ld.volatile.global.u32 %0, [%1];" : "=r"(v) : "l"(&g_bar1));
                    if (v >= (unsigned)(NCTA*(T_STEPS + 1))) break;
                    __nanosleep(64);
                } while (true);
            }
            NBAR();
#pragma unroll 1
            for (int e = tid; e < BATCH*OUTDIM; e += NCOMP) {
                int b = e / OUTDIM, o = e % OUTDIM;
                float s = blin[o];
                const float* hr = g_h1f + (size_t)b*HDIM;
                const float* wr = Wlin + (size_t)o*HDIM;
#pragma unroll 4
                for (int k = 0; k < HDIM; k++) s += hr[k] * wr[k];
                out[b*OUTDIM + o] = s;
            }
        }
    } else {
        // =================== LOADER ROLE (warps 8-11, one per SMSP) ===========
        Ldr L;
        {
            const int lid = tid - NCOMP;            // 0..127
            L.r0  = lid >> 4;                       // 0..7
            const int s16 = lid & 15;
            const int s7  = s16 & 7;
            L.colA = (uint32_t)(((s16 >> 3) << 7) + ((s7 ^ L.r0) << 4));
            L.gA_base = L.r0*HDIM + s16*8;
#pragma unroll
            for (int i = 0; i < 6; i++) {
                int r = L.r0 + 8*i;
                L.wB[i] = ((r / NC) * HDIM + j0 + (r % NC)) * HDIM + s16*8;
            }
            L.lcc = 0;
            L.prev = -1;
        }

#pragma unroll 1
        for (int t = 0; t < T_STEPS; t++) {
            const int p = t & 1;
            lwait(&g_bar0, (unsigned)(NCTA*(t + 1)), lane);
#pragma unroll 1
            for (int s = 0; s < NCHUNK; s++)
                produce(sb, L, g_h0[p], g_Whh0, s*KC);
            lflush(sb, L);                  // publish last G_A chunk
            lwait(&g_bar1, (unsigned)(NCTA*(t + 1)), lane);
#pragma unroll 1
            for (int s = 0; s < NCHUNK; s++)
                produce(sb, L, g_h1[p], g_Whh1, s*KC);
            lflush(sb, L);                  // publish last Whh1 chunk
            lwait(&g_bar0, (unsigned)(NCTA*(t + 2)), lane);
#pragma unroll 1
            for (int s = 0; s < NCHUNK; s++)
                produce(sb, L, g_h0[p ^ 1], g_Wih1, s*KC);
            lflush(sb, L);                  // publish last Wih1 chunk
        }
    }
}

// ---------------- launch ------------------------------------------------------
extern "C" void kernel_launch(void* const* d_in, const int* in_sizes, int n_in,
                              void* d_out, int out_size) {
    const float* x    = (const float*)d_in[0];
    const float* Wih0 = (const float*)d_in[1];
    const float* Whh0 = (const float*)d_in[2];
    const float* bih0 = (const float*)d_in[3];
    const float* bhh0 = (const float*)d_in[4];
    const float* Wih1 = (const float*)d_in[5];
    const float* Whh1 = (const float*)d_in[6];
    const float* bih1 = (const float*)d_in[7];
    const float* bhh1 = (const float*)d_in[8];
    const float* Wlin = (const float*)d_in[9];
    const float* blin = (const float*)d_in[10];

    cudaFuncSetAttribute(lstm_kernel, cudaFuncAttributeMaxDynamicSharedMemorySize, SMEM_DYN);

    int cblocks = (3*WELEMS + 255) / 256;
    convert_kernel<<<cblocks, 256>>>(Whh0, Wih1, Whh1);
    lstm_kernel<<<NCTA, NTHREADS, SMEM_DYN>>>(x, Wih0, bih0, bhh0, bih1, bhh1,
                                              Wlin, blin, (float*)d_out);
}